// round 2
// baseline (speedup 1.0000x reference)
#include <cuda_runtime.h>
#include <math.h>

// ---------------- problem constants ----------------
#define NTOK   16384        // 4 * 4096
#define DIM    1024
#define HID    2048
#define HV2    4096         // 2*HID
#define QK     128
#define G      256
#define NGRP   64           // 4 batches * 16 groups
#define NB     4
#define NGPB   16
#define LN_EPS 1e-5f

// ---------------- scratch (device globals: allocation-guard safe) ----------------
__device__ float g_normed[(size_t)NTOK * DIM];      // 67 MB
__device__ float g_v     [(size_t)NTOK * HID];      // 134 MB
__device__ float g_gate  [(size_t)NTOK * HID];      // 134 MB
__device__ float g_qk    [(size_t)NTOK * QK];       // 8 MB
__device__ float g_qq    [(size_t)NTOK * QK];       // quad_q
__device__ float g_lq    [(size_t)NTOK * QK];       // lin_q
__device__ float g_qkh   [(size_t)NTOK * QK];       // quad_k
__device__ float g_lk    [(size_t)NTOK * QK];       // lin_k
__device__ float g_attn  [(size_t)NGRP * G * G];    // 16.8 MB
__device__ float g_ao    [(size_t)NTOK * HID];      // quad_out then mixed, 134 MB
__device__ float g_linkv [(size_t)NGRP * QK * HID]; // 67 MB

__device__ __forceinline__ float silu(float x) { return x / (1.0f + expf(-x)); }

// ---------------- LayerNorm ----------------
__global__ void ln_kernel(const float* __restrict__ x,
                          const float* __restrict__ w,
                          const float* __restrict__ b) {
    int row = blockIdx.x;
    const float* xr = x + (size_t)row * DIM;
    float s = 0.f, s2 = 0.f;
    for (int i = threadIdx.x; i < DIM; i += blockDim.x) {
        float v = xr[i]; s += v; s2 += v * v;
    }
    __shared__ float sh[8], sh2[8];
    for (int o = 16; o > 0; o >>= 1) {
        s  += __shfl_down_sync(0xffffffffu, s, o);
        s2 += __shfl_down_sync(0xffffffffu, s2, o);
    }
    int wid = threadIdx.x >> 5, lane = threadIdx.x & 31;
    if (lane == 0) { sh[wid] = s; sh2[wid] = s2; }
    __syncthreads();
    if (threadIdx.x == 0) {
        float a = 0.f, a2 = 0.f;
        for (int i = 0; i < (int)(blockDim.x >> 5); i++) { a += sh[i]; a2 += sh2[i]; }
        sh[0] = a; sh2[0] = a2;
    }
    __syncthreads();
    float mu  = sh[0] * (1.0f / DIM);
    float var = sh2[0] * (1.0f / DIM) - mu * mu;
    float inv = rsqrtf(var + LN_EPS);
    float* o = g_normed + (size_t)row * DIM;
    for (int i = threadIdx.x; i < DIM; i += blockDim.x)
        o[i] = (xr[i] - mu) * inv * w[i] + b[i];
}

// ---------------- head offset-scale ----------------
__global__ void heads_kernel(const float* __restrict__ qk_w,
                             const float* __restrict__ qk_b) {
    int i = blockIdx.x * blockDim.x + threadIdx.x;
    if (i >= NTOK * QK) return;
    int d = i & (QK - 1);
    float v = g_qk[i];
    g_qq [i] = v * qk_w[d]          + qk_b[d];
    g_lq [i] = v * qk_w[QK + d]     + qk_b[QK + d];
    g_qkh[i] = v * qk_w[2 * QK + d] + qk_b[2 * QK + d];
    g_lk [i] = v * qk_w[3 * QK + d] + qk_b[3 * QK + d];
}

// ---------------- sim / bias / relu^2 / mask ----------------
__global__ void __launch_bounds__(256) attn_kernel(const float* __restrict__ rel_table) {
    int z  = blockIdx.z;
    int m0 = blockIdx.y * 64, n0 = blockIdx.x * 64;
    const float* Q  = g_qq  + (size_t)z * G * QK;
    const float* Km = g_qkh + (size_t)z * G * QK;
    __shared__ float Qs[16][64];
    __shared__ float Ks[16][64];
    __shared__ float rt[32];
    int tid = threadIdx.x, tx = tid & 15, ty = tid >> 4;
    if (tid < 32) rt[tid] = rel_table[tid] * 11.313708498984761f; // * sqrt(128)
    float acc[4][4] = {};
    for (int d0 = 0; d0 < QK; d0 += 16) {
        int row = tid >> 2, dc = (tid & 3) * 4;
        float4 q  = *(const float4*)&Q [(m0 + row) * QK + d0 + dc];
        float4 k4 = *(const float4*)&Km[(n0 + row) * QK + d0 + dc];
        Qs[dc + 0][row] = q.x;  Qs[dc + 1][row] = q.y;
        Qs[dc + 2][row] = q.z;  Qs[dc + 3][row] = q.w;
        Ks[dc + 0][row] = k4.x; Ks[dc + 1][row] = k4.y;
        Ks[dc + 2][row] = k4.z; Ks[dc + 3][row] = k4.w;
        __syncthreads();
#pragma unroll
        for (int kk = 0; kk < 16; kk++) {
            float ra[4], rb[4];
            *(float4*)ra = *(float4*)&Qs[kk][ty * 4];
            *(float4*)rb = *(float4*)&Ks[kk][tx * 4];
#pragma unroll
            for (int i = 0; i < 4; i++)
#pragma unroll
                for (int j = 0; j < 4; j++)
                    acc[i][j] += ra[i] * rb[j];
        }
        __syncthreads();
    }
    const float inv_lr = 0.48089834696298783f;    // 1/ln(8)
#pragma unroll
    for (int i = 0; i < 4; i++) {
        int gi = m0 + ty * 4 + i;
#pragma unroll
        for (int j = 0; j < 4; j++) {
            int gj = n0 + tx * 4 + j;
            float sim = acc[i][j] * (1.0f / G);
            int n = gi - gj;
            int bucket;
            if (n <= 0)      bucket = 0;
            else if (n < 16) bucket = n;
            else {
                bucket = 16 + (int)(logf((float)n * (1.0f / 16.0f)) * inv_lr * 16.0f);
                if (bucket > 31) bucket = 31;
            }
            sim += rt[bucket];
            float a = sim > 0.f ? sim * sim : 0.f;
            if (gj > gi) a = 0.f;
            g_attn[(size_t)z * (G * G) + gi * G + gj] = a;
        }
    }
}

// ---------------- exclusive group cumsum of lin_kv ----------------
__global__ void cumsum_kernel() {
    int p = blockIdx.x * blockDim.x + threadIdx.x;
    if (p >= NB * QK * HID) return;
    int b = p / (QK * HID);
    int off = p - b * (QK * HID);
    float acc = 0.f;
#pragma unroll
    for (int g = 0; g < NGPB; g++) {
        size_t idx = (size_t)(b * NGPB + g) * (QK * HID) + off;
        float t = g_linkv[idx];
        g_linkv[idx] = acc;
        acc += t;
    }
}

// ---------------- generic 128x128x8 SGEMM with fused epilogues ----------------
// CFG 1: g_normed[16384,1024] @ Wh[1024,4096] + bh -> silu -> split v/gate
// CFG 2: g_normed[16384,1024] @ Wqk[1024,128] + bqk -> silu -> g_qk
// CFG 3: (batched 64) g_attn[256,256] @ g_v[256,2048] -> g_ao
// CFG 4: (batched 64, A^T) g_lk[256,128]^T @ g_v[256,2048] * (1/256) -> g_linkv
// CFG 5: (batched 64) g_lq[256,128] @ g_linkv[128,2048]; g_ao=(g_ao+acc)*g_gate
// CFG 6: g_ao[16384,2048] @ Wout[2048,1024] + bout + x -> out
template <int CFG>
__global__ void __launch_bounds__(256) sgemm_k(const float* __restrict__ pb,
                                               const float* __restrict__ pbias,
                                               const float* __restrict__ paux,
                                               float* __restrict__ out) {
    constexpr int  M = (CFG == 1 || CFG == 2 || CFG == 6) ? NTOK : (CFG == 4 ? QK : G);
    constexpr int  N = (CFG == 1) ? HV2 : (CFG == 2 ? QK : (CFG == 6 ? DIM : HID));
    constexpr int  K = (CFG == 1 || CFG == 2) ? DIM
                     : (CFG == 3 || CFG == 4) ? G
                     : (CFG == 5) ? QK : HID;
    constexpr bool TRANSA = (CFG == 4);
    constexpr float SCALE = (CFG == 4) ? (1.0f / G) : 1.0f;

    int z = blockIdx.z;
    const float* A;
    const float* B;
    if      (CFG == 1 || CFG == 2) { A = g_normed;                       B = pb; }
    else if (CFG == 3)             { A = g_attn + (size_t)z * G * G;     B = g_v + (size_t)z * G * HID; }
    else if (CFG == 4)             { A = g_lk   + (size_t)z * G * QK;    B = g_v + (size_t)z * G * HID; }
    else if (CFG == 5)             { A = g_lq   + (size_t)z * G * QK;    B = g_linkv + (size_t)z * QK * HID; }
    else                           { A = g_ao;                           B = pb; }

    __shared__ float As[8][128];
    __shared__ float Bs[8][128];
    int tid = threadIdx.x;
    int m0 = blockIdx.y * 128, n0 = blockIdx.x * 128;
    int tx = tid & 15, ty = tid >> 4;

    float acc[8][8];
#pragma unroll
    for (int i = 0; i < 8; i++)
#pragma unroll
        for (int j = 0; j < 8; j++) acc[i][j] = 0.f;

    for (int k0 = 0; k0 < K; k0 += 8) {
        if (TRANSA) {
            int kr = tid >> 5, mc = (tid & 31) * 4;
            float4 a = *(const float4*)&A[(k0 + kr) * M + m0 + mc];
            *(float4*)&As[kr][mc] = a;
        } else {
            int row = tid >> 1, kc = (tid & 1) * 4;
            float4 a = *(const float4*)&A[(m0 + row) * K + k0 + kc];
            As[kc + 0][row] = a.x; As[kc + 1][row] = a.y;
            As[kc + 2][row] = a.z; As[kc + 3][row] = a.w;
        }
        {
            int kr = tid >> 5, nc = (tid & 31) * 4;
            float4 b = *(const float4*)&B[(k0 + kr) * N + n0 + nc];
            *(float4*)&Bs[kr][nc] = b;
        }
        __syncthreads();
#pragma unroll
        for (int kk = 0; kk < 8; kk++) {
            float ra[8], rb[8];
            *(float4*)&ra[0] = *(float4*)&As[kk][ty * 4];
            *(float4*)&ra[4] = *(float4*)&As[kk][64 + ty * 4];
            *(float4*)&rb[0] = *(float4*)&Bs[kk][tx * 4];
            *(float4*)&rb[4] = *(float4*)&Bs[kk][64 + tx * 4];
#pragma unroll
            for (int i = 0; i < 8; i++)
#pragma unroll
                for (int j = 0; j < 8; j++)
                    acc[i][j] += ra[i] * rb[j];
        }
        __syncthreads();
    }

#pragma unroll
    for (int i = 0; i < 8; i++) {
        int gm = m0 + ((i < 4) ? (ty * 4 + i) : (64 + ty * 4 + i - 4));
#pragma unroll
        for (int j = 0; j < 8; j++) {
            int gn = n0 + ((j < 4) ? (tx * 4 + j) : (64 + tx * 4 + j - 4));
            float v = acc[i][j] * SCALE;
            if (CFG == 1) {
                float s = silu(v + pbias[gn]);
                if (gn < HID) g_v[(size_t)gm * HID + gn] = s;
                else          g_gate[(size_t)gm * HID + (gn - HID)] = s;
            } else if (CFG == 2) {
                g_qk[(size_t)gm * QK + gn] = silu(v + pbias[gn]);
            } else if (CFG == 3) {
                g_ao[(size_t)z * G * HID + gm * HID + gn] = v;
            } else if (CFG == 4) {
                g_linkv[(size_t)z * QK * HID + gm * HID + gn] = v;
            } else if (CFG == 5) {
                size_t idx = (size_t)z * G * HID + gm * HID + gn;
                g_ao[idx] = (g_ao[idx] + v) * g_gate[idx];
            } else { // CFG == 6
                size_t idx = (size_t)gm * DIM + gn;
                out[idx] = v + pbias[gn] + paux[idx];
            }
        }
    }
}

// ---------------- launch ----------------
extern "C" void kernel_launch(void* const* d_in, const int* in_sizes, int n_in,
                              void* d_out, int out_size) {
    const float* x    = (const float*)d_in[0];
    const float* ln_w = (const float*)d_in[1];
    const float* ln_b = (const float*)d_in[2];
    const float* Wh   = (const float*)d_in[3];
    const float* bh   = (const float*)d_in[4];
    const float* Wqk  = (const float*)d_in[5];
    const float* bqk  = (const float*)d_in[6];
    const float* qk_w = (const float*)d_in[7];
    const float* qk_b = (const float*)d_in[8];
    const float* rel  = (const float*)d_in[9];
    const float* Wout = (const float*)d_in[10];
    const float* bout = (const float*)d_in[11];
    float* out = (float*)d_out;

    // 1) LayerNorm
    ln_kernel<<<NTOK, 256>>>(x, ln_w, ln_b);

    // 2) hv = silu(normed @ Wh + bh) -> v, gate
    sgemm_k<1><<<dim3(HV2 / 128, NTOK / 128, 1), 256>>>(Wh, bh, nullptr, nullptr);

    // 3) qk = silu(normed @ Wqk + bqk)
    sgemm_k<2><<<dim3(QK / 128, NTOK / 128, 1), 256>>>(Wqk, bqk, nullptr, nullptr);

    // 4) four heads
    heads_kernel<<<(NTOK * QK) / 256, 256>>>(qk_w, qk_b);

    // 5) attn = masked relu^2(qq @ qk^T / g + bias)
    attn_kernel<<<dim3(4, 4, NGRP), 256>>>(rel);

    // 6) quad_out = attn @ v
    sgemm_k<3><<<dim3(HID / 128, G / 128, NGRP), 256>>>(nullptr, nullptr, nullptr, nullptr);

    // 7) lin_kv[g] = lin_k^T @ v / g  (per group)
    sgemm_k<4><<<dim3(HID / 128, QK / 128, NGRP), 256>>>(nullptr, nullptr, nullptr, nullptr);

    // 8) exclusive cumsum over groups
    cumsum_kernel<<<(NB * QK * HID) / 256, 256>>>();

    // 9) lin_out = lin_q @ lin_kv ; ao = gate * (quad + lin)
    sgemm_k<5><<<dim3(HID / 128, G / 128, NGRP), 256>>>(nullptr, nullptr, nullptr, nullptr);

    // 10) out = ao @ Wout + bout + x
    sgemm_k<6><<<dim3(DIM / 128, NTOK / 128, 1), 256>>>(Wout, bout, x, out);
}

// round 6
// speedup vs baseline: 3.0933x; 3.0933x over previous
#include <cuda_runtime.h>
#include <math.h>
#include <stdint.h>

// ---------------- problem constants ----------------
#define NTOK   16384        // 4 * 4096
#define DIM    1024
#define HID    2048
#define HV2    4096         // 2*HID
#define QK     128
#define G      256
#define NGRP   64           // 4 batches * 16 groups
#define NB     4
#define NGPB   16
#define LN_EPS 1e-5f

// ---------------- scratch (device globals) ----------------
__device__ float g_normed[(size_t)NTOK * DIM];
__device__ float g_vT    [(size_t)NGRP * HID * G];   // v transposed per group: [g][e][t]
__device__ float g_gate  [(size_t)NTOK * HID];
__device__ float g_qk    [(size_t)NTOK * QK];
__device__ float g_qq    [(size_t)NTOK * QK];        // [g][t][d]
__device__ float g_lq    [(size_t)NTOK * QK];
__device__ float g_qkh   [(size_t)NTOK * QK];
__device__ float g_lkT   [(size_t)NGRP * QK * G];    // lin_k transposed: [g][d][t]
__device__ float g_attn  [(size_t)NGRP * G * G];
__device__ float g_ao    [(size_t)NTOK * HID];
__device__ float g_linkv [(size_t)NGRP * HID * QK];  // [g][e][d]
__device__ float g_WhT   [(size_t)HV2 * DIM];
__device__ float g_WqkT  [(size_t)QK * DIM];
__device__ float g_WoutT [(size_t)DIM * HID];

__device__ __forceinline__ float silu(float x) { return x / (1.0f + expf(-x)); }
// round-to-nearest tf32 (removes HMMA truncation bias)
__device__ __forceinline__ float rtf(float f) {
    uint32_t u;
    asm("cvt.rna.tf32.f32 %0, %1;" : "=r"(u) : "f"(f));
    return __uint_as_float(u);
}

// ---------------- LayerNorm (tf32-rounded output: GEMM operand) ----------------
__global__ void ln_kernel(const float* __restrict__ x,
                          const float* __restrict__ w,
                          const float* __restrict__ b) {
    int row = blockIdx.x;
    const float* xr = x + (size_t)row * DIM;
    float s = 0.f, s2 = 0.f;
    for (int i = threadIdx.x; i < DIM; i += blockDim.x) {
        float v = xr[i]; s += v; s2 += v * v;
    }
    __shared__ float sh[8], sh2[8];
    for (int o = 16; o > 0; o >>= 1) {
        s  += __shfl_down_sync(0xffffffffu, s, o);
        s2 += __shfl_down_sync(0xffffffffu, s2, o);
    }
    int wid = threadIdx.x >> 5, lane = threadIdx.x & 31;
    if (lane == 0) { sh[wid] = s; sh2[wid] = s2; }
    __syncthreads();
    if (threadIdx.x == 0) {
        float a = 0.f, a2 = 0.f;
        for (int i = 0; i < (int)(blockDim.x >> 5); i++) { a += sh[i]; a2 += sh2[i]; }
        sh[0] = a; sh2[0] = a2;
    }
    __syncthreads();
    float mu  = sh[0] * (1.0f / DIM);
    float var = sh2[0] * (1.0f / DIM) - mu * mu;
    float inv = rsqrtf(var + LN_EPS);
    float* o = g_normed + (size_t)row * DIM;
    for (int i = threadIdx.x; i < DIM; i += blockDim.x)
        o[i] = rtf((xr[i] - mu) * inv * w[i] + b[i]);
}

// ---------------- tiled transpose + tf32 rounding: in[R][C] -> out[C][R] ----------------
__global__ void transpose_k(const float* __restrict__ in, float* __restrict__ out,
                            int R, int C) {
    __shared__ float t[32][33];
    int c0 = blockIdx.x * 32, r0 = blockIdx.y * 32;
    int x = threadIdx.x, y = threadIdx.y;
#pragma unroll
    for (int j = 0; j < 32; j += 8)
        t[y + j][x] = in[(size_t)(r0 + y + j) * C + c0 + x];
    __syncthreads();
#pragma unroll
    for (int j = 0; j < 32; j += 8)
        out[(size_t)(c0 + y + j) * R + r0 + x] = rtf(t[x][y + j]);
}

// ---------------- heads: qk -> qq, qkh (fp32, FFMA consumer) + lq, lkT (tf32) ----------------
__global__ void __launch_bounds__(256) heads_kernel(const float* __restrict__ qk_w,
                                                    const float* __restrict__ qk_b) {
    __shared__ float sm[128][65];
    int t0 = blockIdx.x * 64;
#pragma unroll 4
    for (int i = 0; i < 32; ++i) {
        int idx = threadIdx.x + i * 256;        // 64*128
        int tl = idx >> 7, d = idx & 127;
        int tok = t0 + tl;
        float v = g_qk[(size_t)tok * QK + d];
        g_qq [(size_t)tok * QK + d] = v * qk_w[d]           + qk_b[d];
        g_lq [(size_t)tok * QK + d] = rtf(v * qk_w[QK + d]  + qk_b[QK + d]);
        g_qkh[(size_t)tok * QK + d] = v * qk_w[2 * QK + d]  + qk_b[2 * QK + d];
        sm[d][tl] = rtf(v * qk_w[3 * QK + d] + qk_b[3 * QK + d]);
    }
    __syncthreads();
    int grp = t0 >> 8, tg0 = t0 & 255;
#pragma unroll 4
    for (int i = 0; i < 32; ++i) {
        int idx = threadIdx.x + i * 256;
        int d = idx >> 6, tl = idx & 63;
        g_lkT[((size_t)grp * QK + d) * G + tg0 + tl] = sm[d][tl];
    }
}

// ---------------- sim / bias / relu^2 / mask (fp32 math, tf32-rounded output) ----------------
__global__ void __launch_bounds__(256) attn_kernel(const float* __restrict__ rel_table) {
    int z  = blockIdx.z;
    int m0 = blockIdx.y * 64, n0 = blockIdx.x * 64;
    const float* Q  = g_qq  + (size_t)z * G * QK;
    const float* Km = g_qkh + (size_t)z * G * QK;
    __shared__ float Qs[16][64];
    __shared__ float Ks[16][64];
    __shared__ float rt[32];
    int tid = threadIdx.x, tx = tid & 15, ty = tid >> 4;
    if (tid < 32) rt[tid] = rel_table[tid] * 11.313708498984761f;
    float acc[4][4] = {};
    for (int d0 = 0; d0 < QK; d0 += 16) {
        int row = tid >> 2, dc = (tid & 3) * 4;
        float4 q  = *(const float4*)&Q [(m0 + row) * QK + d0 + dc];
        float4 k4 = *(const float4*)&Km[(n0 + row) * QK + d0 + dc];
        Qs[dc + 0][row] = q.x;  Qs[dc + 1][row] = q.y;
        Qs[dc + 2][row] = q.z;  Qs[dc + 3][row] = q.w;
        Ks[dc + 0][row] = k4.x; Ks[dc + 1][row] = k4.y;
        Ks[dc + 2][row] = k4.z; Ks[dc + 3][row] = k4.w;
        __syncthreads();
#pragma unroll
        for (int kk = 0; kk < 16; kk++) {
            float ra[4], rb[4];
            *(float4*)ra = *(float4*)&Qs[kk][ty * 4];
            *(float4*)rb = *(float4*)&Ks[kk][tx * 4];
#pragma unroll
            for (int i = 0; i < 4; i++)
#pragma unroll
                for (int j = 0; j < 4; j++)
                    acc[i][j] += ra[i] * rb[j];
        }
        __syncthreads();
    }
    const float inv_lr = 0.48089834696298783f;
#pragma unroll
    for (int i = 0; i < 4; i++) {
        int gi = m0 + ty * 4 + i;
#pragma unroll
        for (int j = 0; j < 4; j++) {
            int gj = n0 + tx * 4 + j;
            float sim = acc[i][j] * (1.0f / G);
            int n = gi - gj;
            int bucket;
            if (n <= 0)      bucket = 0;
            else if (n < 16) bucket = n;
            else {
                bucket = 16 + (int)(logf((float)n * (1.0f / 16.0f)) * inv_lr * 16.0f);
                if (bucket > 31) bucket = 31;
            }
            sim += rt[bucket];
            float a = sim > 0.f ? sim * sim : 0.f;
            if (gj > gi) a = 0.f;
            g_attn[(size_t)z * (G * G) + gi * G + gj] = rtf(a);
        }
    }
}

// ---------------- exclusive group cumsum of lin_kv (tf32-rounded output) ----------------
__global__ void cumsum_kernel() {
    int p = blockIdx.x * blockDim.x + threadIdx.x;
    if (p >= NB * QK * HID) return;
    int b = p / (QK * HID);
    int off = p - b * (QK * HID);
    float acc = 0.f;
#pragma unroll
    for (int g = 0; g < NGPB; g++) {
        size_t idx = (size_t)(b * NGPB + g) * (QK * HID) + off;
        float t = g_linkv[idx];
        g_linkv[idx] = rtf(acc);
        acc += t;
    }
}

// ---------------- tf32 mma.sync GEMM, 128x128 CTA tile, K-chunk 32 ----------------
// D[m][n] = sum_k A[m][k]*B[n][k], both operands K-major (row.col for mma.sync)
// CFG 1: A=g_normed, B=g_WhT,   M=16384,N=4096,K=1024; silu(+bh); n<2048 -> g_vT (transposed), else g_gate
// CFG 2: A=g_normed, B=g_WqkT,  M=16384,N=128, K=1024; silu(+bqk) -> g_qk
// CFG 3: A=g_attn[z], B=g_vT[z],   M=256, N=2048,K=256; -> g_ao
// CFG 4: A=g_vT[z],  B=g_lkT[z],   M=2048,N=128, K=256; *(1/256) -> g_linkv [e][d]
// CFG 5: A=g_lq[z],  B=g_linkv[z], M=256, N=2048,K=128; g_ao=rtf((g_ao+v)*g_gate)
// CFG 6: A=g_ao,     B=g_WoutT,  M=16384,N=1024,K=2048; +bout+x -> out
#define STG     18432                       // one 128x32 operand stage (stride 36 floats)
#define GEMM_SMEM (4 * STG)                 // 73728: As0,Bs0,As1,Bs1 (epilogue reuses)

__device__ __forceinline__ uint32_t smem_u32(const void* p) {
    uint32_t a;
    asm("{ .reg .u64 t; cvta.to.shared.u64 t, %1; cvt.u32.u64 %0, t; }" : "=r"(a) : "l"(p));
    return a;
}
__device__ __forceinline__ void mma8(float* d, const uint32_t* a, const uint32_t* b) {
    asm volatile(
        "mma.sync.aligned.m16n8k8.row.col.f32.tf32.tf32.f32 "
        "{%0,%1,%2,%3}, {%4,%5,%6,%7}, {%8,%9}, {%0,%1,%2,%3};"
        : "+f"(d[0]), "+f"(d[1]), "+f"(d[2]), "+f"(d[3])
        : "r"(a[0]), "r"(a[1]), "r"(a[2]), "r"(a[3]), "r"(b[0]), "r"(b[1]));
}

template <int CFG>
__global__ void __launch_bounds__(256)
gemm_tc(const float* __restrict__ pbias, const float* __restrict__ paux,
        float* __restrict__ pout) {
    constexpr int K  = (CFG == 1 || CFG == 2) ? 1024
                     : (CFG == 3 || CFG == 4) ? 256
                     : (CFG == 5) ? 128 : 2048;
    constexpr int NC = K / 32;

    extern __shared__ char smem[];
    uint32_t sbase = smem_u32(smem);
    float* smf = (float*)smem;

    int tid = threadIdx.x, w = tid >> 5, lane = tid & 31;
    int grpL = lane >> 2, tig = lane & 3;
    int wm = w >> 2, wn = w & 3;            // 2 x 4 warp grid
    int z = blockIdx.z;
    int n0 = blockIdx.x * 128, m0 = blockIdx.y * 128;

    const float* A; const float* B;
    if      (CFG == 1) { A = g_normed;                     B = g_WhT;  }
    else if (CFG == 2) { A = g_normed;                     B = g_WqkT; }
    else if (CFG == 3) { A = g_attn + (size_t)z * G * G;   B = g_vT + (size_t)z * HID * G; }
    else if (CFG == 4) { A = g_vT + (size_t)z * HID * G;   B = g_lkT + (size_t)z * QK * G; }
    else if (CFG == 5) { A = g_lq + (size_t)z * G * QK;    B = g_linkv + (size_t)z * HID * QK; }
    else               { A = g_ao;                         B = g_WoutT; }

    float acc[4][4][4];
#pragma unroll
    for (int i = 0; i < 4; i++)
#pragma unroll
        for (int j = 0; j < 4; j++)
#pragma unroll
            for (int r = 0; r < 4; r++) acc[i][j][r] = 0.f;

    int ldr = tid >> 3, ldc = (tid & 7) * 4;          // global->smem mapping

    // prime stage 0
    {
        const float* Ap = A + (size_t)m0 * K;
        const float* Bp = B + (size_t)n0 * K;
#pragma unroll
        for (int j = 0; j < 4; ++j) {
            int r = ldr + j * 32;
            uint32_t da = sbase + (uint32_t)((r * 36 + ldc) * 4);
            uint32_t db = da + STG;
            asm volatile("cp.async.cg.shared.global [%0], [%1], 16;"
                         :: "r"(da), "l"(Ap + (size_t)r * K + ldc));
            asm volatile("cp.async.cg.shared.global [%0], [%1], 16;"
                         :: "r"(db), "l"(Bp + (size_t)r * K + ldc));
        }
        asm volatile("cp.async.commit_group;");
    }

    for (int c = 0; c < NC; ++c) {
        if (c + 1 < NC) {
            int st = (c + 1) & 1;
            const float* Ap = A + (size_t)m0 * K + (c + 1) * 32;
            const float* Bp = B + (size_t)n0 * K + (c + 1) * 32;
#pragma unroll
            for (int j = 0; j < 4; ++j) {
                int r = ldr + j * 32;
                uint32_t da = sbase + (uint32_t)(st * 2 * STG + (r * 36 + ldc) * 4);
                uint32_t db = da + STG;
                asm volatile("cp.async.cg.shared.global [%0], [%1], 16;"
                             :: "r"(da), "l"(Ap + (size_t)r * K + ldc));
                asm volatile("cp.async.cg.shared.global [%0], [%1], 16;"
                             :: "r"(db), "l"(Bp + (size_t)r * K + ldc));
            }
            asm volatile("cp.async.commit_group;");
            asm volatile("cp.async.wait_group 1;");
        } else {
            asm volatile("cp.async.wait_group 0;");
        }
        __syncthreads();

        const uint32_t* As = (const uint32_t*)(smem + (c & 1) * 2 * STG);
        const uint32_t* Bs = As + STG / 4;
#pragma unroll
        for (int k8 = 0; k8 < 4; ++k8) {
            int k0 = k8 * 8;
            uint32_t af[4][4], bf[4][2];
#pragma unroll
            for (int i = 0; i < 4; ++i) {
                int rb = wm * 64 + i * 16 + grpL;
                af[i][0] = As[rb * 36 + k0 + tig];
                af[i][1] = As[(rb + 8) * 36 + k0 + tig];
                af[i][2] = As[rb * 36 + k0 + tig + 4];
                af[i][3] = As[(rb + 8) * 36 + k0 + tig + 4];
            }
#pragma unroll
            for (int j = 0; j < 4; ++j) {
                int nb = wn * 32 + j * 8 + grpL;
                bf[j][0] = Bs[nb * 36 + k0 + tig];
                bf[j][1] = Bs[nb * 36 + k0 + tig + 4];
            }
#pragma unroll
            for (int i = 0; i < 4; ++i)
#pragma unroll
                for (int j = 0; j < 4; ++j)
                    mma8(acc[i][j], af[i], bf[j]);
        }
        __syncthreads();
    }

    // ---- stage accumulators into smem [128][132] ----
#pragma unroll
    for (int i = 0; i < 4; ++i) {
#pragma unroll
        for (int j = 0; j < 4; ++j) {
            int row = wm * 64 + i * 16 + grpL;
            int col = wn * 32 + j * 8 + tig * 2;
            smf[row * 132 + col]           = acc[i][j][0];
            smf[row * 132 + col + 1]       = acc[i][j][1];
            smf[(row + 8) * 132 + col]     = acc[i][j][2];
            smf[(row + 8) * 132 + col + 1] = acc[i][j][3];
        }
    }
    __syncthreads();

    // ---- epilogue / global write ----
    if (CFG == 1 && n0 < HID) {
        // v branch: write transposed into g_vT[grp][gn][t] (tf32-rounded: GEMM operand)
        int grp = m0 >> 8, tg0 = m0 & 255;
#pragma unroll
        for (int it = 0; it < 16; ++it) {
            int cc = it * 8 + w;               // 0..127
            int gn = n0 + cc;
            float bias = pbias[gn];
            int t = lane * 4;
            float4 o;
            o.x = rtf(silu(smf[(t + 0) * 132 + cc] + bias));
            o.y = rtf(silu(smf[(t + 1) * 132 + cc] + bias));
            o.z = rtf(silu(smf[(t + 2) * 132 + cc] + bias));
            o.w = rtf(silu(smf[(t + 3) * 132 + cc] + bias));
            *(float4*)&g_vT[((size_t)grp * HID + gn) * G + tg0 + t] = o;
        }
        return;
    }
#pragma unroll
    for (int it = 0; it < 16; ++it) {
        int idx = tid + it * 256;              // 4096 float4 slots
        int r = idx >> 5, c4 = (idx & 31) * 4;
        int gm = m0 + r, gn = n0 + c4;
        float v0 = smf[r * 132 + c4 + 0];
        float v1 = smf[r * 132 + c4 + 1];
        float v2 = smf[r * 132 + c4 + 2];
        float v3 = smf[r * 132 + c4 + 3];
        if (CFG == 1) {                        // gate branch (n0 >= HID): fp32 consumer
            float4 o;
            o.x = silu(v0 + pbias[gn + 0]); o.y = silu(v1 + pbias[gn + 1]);
            o.z = silu(v2 + pbias[gn + 2]); o.w = silu(v3 + pbias[gn + 3]);
            *(float4*)&g_gate[(size_t)gm * HID + (gn - HID)] = o;
        } else if (CFG == 2) {                 // fp32 consumer (heads)
            float4 o;
            o.x = silu(v0 + pbias[gn + 0]); o.y = silu(v1 + pbias[gn + 1]);
            o.z = silu(v2 + pbias[gn + 2]); o.w = silu(v3 + pbias[gn + 3]);
            *(float4*)&g_qk[(size_t)gm * QK + gn] = o;
        } else if (CFG == 3) {                 // fp32 consumer (CFG5 epilogue)
            float4 o = make_float4(v0, v1, v2, v3);
            *(float4*)&g_ao[((size_t)z * G + gm) * HID + gn] = o;
        } else if (CFG == 4) {                 // cumsum rounds later
            float4 o = make_float4(v0 * (1.0f / G), v1 * (1.0f / G),
                                   v2 * (1.0f / G), v3 * (1.0f / G));
            *(float4*)&g_linkv[((size_t)z * HID + gm) * QK + gn] = o;
        } else if (CFG == 5) {                 // tf32-rounded: feeds CFG6 A
            size_t i0 = ((size_t)z * G + gm) * HID + gn;
            float4 q = *(const float4*)&g_ao[i0];
            float4 gt = *(const float4*)&g_gate[i0];
            float4 o;
            o.x = rtf((q.x + v0) * gt.x); o.y = rtf((q.y + v1) * gt.y);
            o.z = rtf((q.z + v2) * gt.z); o.w = rtf((q.w + v3) * gt.w);
            *(float4*)&g_ao[i0] = o;
        } else {                               // CFG 6
            size_t i0 = (size_t)gm * DIM + gn;
            float4 xr = *(const float4*)&paux[i0];
            float4 o;
            o.x = v0 + pbias[gn + 0] + xr.x; o.y = v1 + pbias[gn + 1] + xr.y;
            o.z = v2 + pbias[gn + 2] + xr.z; o.w = v3 + pbias[gn + 3] + xr.w;
            *(float4*)&pout[i0] = o;
        }
    }
}

// ---------------- launch ----------------
extern "C" void kernel_launch(void* const* d_in, const int* in_sizes, int n_in,
                              void* d_out, int out_size) {
    const float* x    = (const float*)d_in[0];
    const float* ln_w = (const float*)d_in[1];
    const float* ln_b = (const float*)d_in[2];
    const float* Wh   = (const float*)d_in[3];
    const float* bh   = (const float*)d_in[4];
    const float* Wqk  = (const float*)d_in[5];
    const float* bqk  = (const float*)d_in[6];
    const float* qk_w = (const float*)d_in[7];
    const float* qk_b = (const float*)d_in[8];
    const float* rel  = (const float*)d_in[9];
    const float* Wout = (const float*)d_in[10];
    const float* bout = (const float*)d_in[11];
    float* out = (float*)d_out;

    cudaFuncSetAttribute(gemm_tc<1>, cudaFuncAttributeMaxDynamicSharedMemorySize, GEMM_SMEM);
    cudaFuncSetAttribute(gemm_tc<2>, cudaFuncAttributeMaxDynamicSharedMemorySize, GEMM_SMEM);
    cudaFuncSetAttribute(gemm_tc<3>, cudaFuncAttributeMaxDynamicSharedMemorySize, GEMM_SMEM);
    cudaFuncSetAttribute(gemm_tc<4>, cudaFuncAttributeMaxDynamicSharedMemorySize, GEMM_SMEM);
    cudaFuncSetAttribute(gemm_tc<5>, cudaFuncAttributeMaxDynamicSharedMemorySize, GEMM_SMEM);
    cudaFuncSetAttribute(gemm_tc<6>, cudaFuncAttributeMaxDynamicSharedMemorySize, GEMM_SMEM);

    float* WhT;   cudaGetSymbolAddress((void**)&WhT,   g_WhT);
    float* WqkT;  cudaGetSymbolAddress((void**)&WqkT,  g_WqkT);
    float* WoutT; cudaGetSymbolAddress((void**)&WoutT, g_WoutT);

    // weight transposes (K-major B operands, tf32-rounded)
    transpose_k<<<dim3(HV2 / 32, DIM / 32), dim3(32, 8)>>>(Wh,   WhT,   DIM, HV2);
    transpose_k<<<dim3(QK  / 32, DIM / 32), dim3(32, 8)>>>(Wqk,  WqkT,  DIM, QK);
    transpose_k<<<dim3(DIM / 32, HID / 32), dim3(32, 8)>>>(Wout, WoutT, HID, DIM);

    // 1) LayerNorm
    ln_kernel<<<NTOK, 256>>>(x, ln_w, ln_b);

    // 2) hv = silu(normed @ Wh + bh) -> vT (transposed) + gate
    gemm_tc<1><<<dim3(HV2 / 128, NTOK / 128, 1), 256, GEMM_SMEM>>>(bh, nullptr, nullptr);

    // 3) qk = silu(normed @ Wqk + bqk)
    gemm_tc<2><<<dim3(1, NTOK / 128, 1), 256, GEMM_SMEM>>>(bqk, nullptr, nullptr);

    // 4) heads (+ lin_k transpose)
    heads_kernel<<<NTOK / 64, 256>>>(qk_w, qk_b);

    // 5) attn scores
    attn_kernel<<<dim3(4, 4, NGRP), 256>>>(rel);

    // 6) quad_out = attn @ v
    gemm_tc<3><<<dim3(HID / 128, G / 128, NGRP), 256, GEMM_SMEM>>>(nullptr, nullptr, nullptr);

    // 7) lin_kv = v^T @ lin_k / g   -> [e][d]
    gemm_tc<4><<<dim3(1, HID / 128, NGRP), 256, GEMM_SMEM>>>(nullptr, nullptr, nullptr);

    // 8) exclusive group cumsum
    cumsum_kernel<<<(NB * QK * HID) / 256, 256>>>();

    // 9) lin_out = lin_q @ lin_kv ; ao = gate*(quad+lin)
    gemm_tc<5><<<dim3(HID / 128, G / 128, NGRP), 256, GEMM_SMEM>>>(nullptr, nullptr, nullptr);

    // 10) out = ao @ Wout + bout + x
    gemm_tc<6><<<dim3(DIM / 128, NTOK / 128, 1), 256, GEMM_SMEM>>>(bout, x, out);
}